// round 7
// baseline (speedup 1.0000x reference)
#include <cuda_runtime.h>
#include <cuda_bf16.h>
#include <cstdint>

#define N_TOK 8192
#define C_CH  64
#define CR_   32
#define NSPLIT 2

// Scratch
__device__ unsigned g_qT[N_TOK * 16];               // [8192][32] bf16, scaled by sqrt(log2e)*32^-0.25
__device__ float    g_Z[N_TOK];                     // row sums of exp(S)
__device__ unsigned g_vp[C_CH * 4096];              // [64][8192] bf16 = x / Z[n]
__device__ __align__(16) float g_P[NSPLIT * C_CH * N_TOK];  // split partials (4MB)

// ---------------- helpers ----------------
static __device__ __forceinline__ float ex2f(float x) {
    float r;
    asm("ex2.approx.f32 %0, %1;" : "=f"(r) : "f"(x));
    return r;
}

static __device__ __forceinline__ unsigned packbf(float lo, float hi) {
    unsigned u;
    asm("cvt.rn.bf16x2.f32 %0, %1, %2;" : "=r"(u) : "f"(hi), "f"(lo));
    return u;
}

static __device__ __forceinline__ void mma16816(float d[4], const unsigned a[4], const unsigned b[2]) {
    asm("mma.sync.aligned.m16n8k16.row.col.f32.bf16.bf16.f32 "
        "{%0,%1,%2,%3}, {%4,%5,%6,%7}, {%8,%9}, {%0,%1,%2,%3};"
        : "+f"(d[0]), "+f"(d[1]), "+f"(d[2]), "+f"(d[3])
        : "r"(a[0]), "r"(a[1]), "r"(a[2]), "r"(a[3]), "r"(b[0]), "r"(b[1]));
}

static __device__ __forceinline__ void ldsm4(unsigned& r0, unsigned& r1, unsigned& r2, unsigned& r3,
                                             unsigned saddr) {
    asm volatile("ldmatrix.sync.aligned.m8n8.x4.shared.b16 {%0,%1,%2,%3}, [%4];"
                 : "=r"(r0), "=r"(r1), "=r"(r2), "=r"(r3) : "r"(saddr));
}

static __device__ __forceinline__ void cpasync16(unsigned saddr, const void* gsrc) {
    asm volatile("cp.async.cg.shared.global [%0], [%1], 16;" :: "r"(saddr), "l"(gsrc));
}

static __device__ __forceinline__ int swz(int r, int w) {
    return (((w >> 2) ^ (r & 7)) << 2) | (w & 3);
}

// ---------------- K1: qT = (W@x + bias) * sqrt(log2e)*32^-0.25, zero Z ----------------
__global__ void k1_qproj(const float* __restrict__ x, const float* __restrict__ W,
                         const float* __restrict__ bias) {
    __shared__ float sW[CR_ * 64];
    __shared__ float sb[CR_];
    int tid = threadIdx.x;
    for (int i = tid; i < CR_ * 64; i += 256) sW[i] = W[i];
    if (tid < CR_) sb[tid] = bias[tid];
    __syncthreads();

    int n = blockIdx.x * 256 + tid;
    float q[CR_];
#pragma unroll
    for (int k = 0; k < CR_; k++) q[k] = sb[k];
#pragma unroll 4
    for (int c = 0; c < 64; c++) {
        float xv = x[c * N_TOK + n];
#pragma unroll
        for (int k = 0; k < CR_; k++) q[k] = fmaf(sW[k * 64 + c], xv, q[k]);
    }
    const float sc = 0.5050097687177836f;  // 32^-0.25 * sqrt(log2 e)
    unsigned* dst = g_qT + n * 16;
#pragma unroll
    for (int k = 0; k < 16; k++) dst[k] = packbf(q[2 * k] * sc, q[2 * k + 1] * sc);
    g_Z[n] = 0.0f;
}

// ---------------- KA: Z via 512x512 supertiles, triangular (136 CTAs) ----------------
// Stage q strips once (64KB), sweep <=16 subtiles of 128x128, accumulate Z in smem.
#define SMEM_KA_BYTES 69632
__global__ void __launch_bounds__(512, 1) kA_zsum() {
    extern __shared__ __align__(16) unsigned dsm[];
    unsigned* sQI = dsm;             // 512 rows x 16 words
    unsigned* sQJ = dsm + 8192;
    float*    sZ  = (float*)(dsm + 16384);   // [2][512]

    // bid -> (I, J), I <= J over 16 strips
    int I = 0, rem = blockIdx.x;
    while (rem >= 16 - I) { rem -= 16 - I; I++; }
    const int J = I + rem;

    const int tid = threadIdx.x;
    const int l = tid & 31, w = tid >> 5;
    const int g = l >> 2, t = l & 3;
    const int wm = w >> 2, wn = w & 3;      // 4m x 4n, warp tile 32x32
    const unsigned sqib = (unsigned)__cvta_generic_to_shared(sQI);
    const unsigned sqjb = (unsigned)__cvta_generic_to_shared(sQJ);

    // zero sZ
    for (int i = tid; i < 1024; i += 512) sZ[i] = 0.0f;

    // stage both strips: 512 rows x 4 chunks each
#pragma unroll
    for (int i2 = 0; i2 < 4; i2++) {
        int idx = i2 * 512 + tid;
        int r = idx >> 2, ch = idx & 3;
        int cc = ch ^ ((r >> 1) & 3);
        cpasync16(sqib + (r * 16 + cc * 4) * 4, g_qT + (I * 512 + r) * 16 + ch * 4);
    }
#pragma unroll
    for (int i2 = 0; i2 < 4; i2++) {
        int idx = i2 * 512 + tid;
        int r = idx >> 2, ch = idx & 3;
        int cc = ch ^ ((r >> 1) & 3);
        cpasync16(sqjb + (r * 16 + cc * 4) * 4, g_qT + (J * 512 + r) * 16 + ch * 4);
    }
    asm volatile("cp.async.commit_group;" ::);
    asm volatile("cp.async.wait_group 0;" ::);
    __syncthreads();

    const int zj = (I == J) ? 0 : 1;

    for (int s = 0; s < 16; s++) {
        const int si = s >> 2, sj = s & 3;
        if (I == J && sj < si) continue;
        const bool diag = (I == J && si == sj);

        // a frags: warp rows si*128 + wm*32 + mi*16
        unsigned a[2][2][4];
#pragma unroll
        for (int mi = 0; mi < 2; mi++) {
            int r = si * 128 + wm * 32 + mi * 16 + (l & 15);
            int c0 = ((l >> 4))     ^ ((r >> 1) & 3);
            int c1 = (2 + (l >> 4)) ^ ((r >> 1) & 3);
            ldsm4(a[mi][0][0], a[mi][0][1], a[mi][0][2], a[mi][0][3], sqib + (r * 16 + c0 * 4) * 4);
            ldsm4(a[mi][1][0], a[mi][1][1], a[mi][1][2], a[mi][1][3], sqib + (r * 16 + c1 * 4) * 4);
        }
        // b frags: warp cols sj*128 + wn*32 + gi*16
        unsigned v[2][2][4];
#pragma unroll
        for (int gi = 0; gi < 2; gi++) {
            int r = sj * 128 + wn * 32 + gi * 16 + (l & 15);
            int c0 = ((l >> 4))     ^ ((r >> 1) & 3);
            int c1 = (2 + (l >> 4)) ^ ((r >> 1) & 3);
            ldsm4(v[gi][0][0], v[gi][0][1], v[gi][0][2], v[gi][0][3], sqjb + (r * 16 + c0 * 4) * 4);
            ldsm4(v[gi][1][0], v[gi][1][1], v[gi][1][2], v[gi][1][3], sqjb + (r * 16 + c1 * 4) * 4);
        }

        float rs[2][2], cs[4][2];
#pragma unroll
        for (int i = 0; i < 2; i++) { rs[i][0] = rs[i][1] = 0.0f; }
#pragma unroll
        for (int i = 0; i < 4; i++) { cs[i][0] = cs[i][1] = 0.0f; }

#pragma unroll
        for (int mi = 0; mi < 2; mi++)
#pragma unroll
            for (int gi = 0; gi < 2; gi++)
#pragma unroll
                for (int h = 0; h < 2; h++) {
                    float acc[4] = {0.0f, 0.0f, 0.0f, 0.0f};
                    unsigned b0[2] = {v[gi][0][h], v[gi][0][h + 2]};
                    unsigned b1[2] = {v[gi][1][h], v[gi][1][h + 2]};
                    mma16816(acc, a[mi][0], b0);
                    mma16816(acc, a[mi][1], b1);
                    float e0 = ex2f(acc[0]);
                    float e1 = ex2f(acc[1]);
                    float e2 = ex2f(acc[2]);
                    float e3 = ex2f(acc[3]);
                    rs[mi][0] += e0 + e1;
                    rs[mi][1] += e2 + e3;
                    int ni = gi * 2 + h;
                    cs[ni][0] += e0 + e2;
                    cs[ni][1] += e1 + e3;
                }

        // row sums -> sZ[0] strip I
#pragma unroll
        for (int mi = 0; mi < 2; mi++)
#pragma unroll
            for (int r = 0; r < 2; r++) {
                float vv = rs[mi][r];
                vv += __shfl_xor_sync(0xffffffffu, vv, 1);
                vv += __shfl_xor_sync(0xffffffffu, vv, 2);
                if (t == 0)
                    atomicAdd(&sZ[si * 128 + wm * 32 + mi * 16 + r * 8 + g], vv);
            }
        // col sums -> strip J (mirror), skip on diagonal subtiles
        if (!diag) {
#pragma unroll
            for (int ni = 0; ni < 4; ni++)
#pragma unroll
                for (int p = 0; p < 2; p++) {
                    float vv = cs[ni][p];
                    vv += __shfl_xor_sync(0xffffffffu, vv, 4);
                    vv += __shfl_xor_sync(0xffffffffu, vv, 8);
                    vv += __shfl_xor_sync(0xffffffffu, vv, 16);
                    if (l < 4)
                        atomicAdd(&sZ[zj * 512 + sj * 128 + wn * 32 + ni * 8 + 2 * t + p], vv);
                }
        }
    }

    __syncthreads();
    atomicAdd(&g_Z[I * 512 + tid], sZ[tid]);
    if (J != I) atomicAdd(&g_Z[J * 512 + tid], sZ[512 + tid]);
}

// ---------------- K2b: vp[c][n] = bf16(x[c][n] / Z[n]) ----------------
__global__ void k2b_vprep(const float* __restrict__ x) {
    int wdx = blockIdx.x * 256 + threadIdx.x;
    int c  = wdx >> 12;
    int nw = wdx & 4095;
    int n  = nw * 2;
    float v0 = x[c * N_TOK + n]     / g_Z[n];
    float v1 = x[c * N_TOK + n + 1] / g_Z[n + 1];
    g_vp[wdx] = packbf(v0, v1);
}

// ---------------- KB: fused, warp-specialized ----------------
// Warps 0-7 (P): phase1 S->ex2->sE (MUFU-heavy). Warps 8-15 (C): phase2
// out += sE @ vp (tensor-heavy). 2+2 warps per SMSP -> pipes overlap.
#define SMEM_KB_BYTES 139264
__global__ void __launch_bounds__(512, 1) kB_fused() {
    extern __shared__ __align__(16) unsigned smem[];
    const unsigned OFF_E  = 0;              // 2 * 128*64 = 16384 words
    const unsigned OFF_VP = 16384;          // 3 * 64*64  = 12288 words
    const unsigned OFF_Q  = 28672;          // 3 * 128*16 =  6144 words

    const int tid = threadIdx.x;
    const int l = tid & 31, w = tid >> 5;   // w 0..15
    const int g = l >> 2, t = l & 3;
    const bool isP = (w < 8);
    const int m0 = blockIdx.x * 128;
    const int ntbase = blockIdx.y * 32;

    const unsigned sb = (unsigned)__cvta_generic_to_shared(smem);

    // ---- producer state ----
    const int wmP = w >> 2, wnP = w & 3;    // 2(m64) x 4(n32)
    unsigned ap[4][2][4];
    // ---- consumer state ----
    const int cw = w - 8;
    const int wm2 = cw & 3, nh = cw >> 2;   // 4(m32) x 2(n-half)
    float acc[2][8][4];

    auto issueQ = [&](int itq) {            // stage qT tile ntbase+itq into slot itq%3
        if (itq <= 31) {
            int slot = itq % 3;
#pragma unroll
            for (int i2 = 0; i2 < 2; i2++) {
                int idx = i2 * 256 + tid;   // tid 0..255 for P
                int r = idx >> 2, c = idx & 3;
                int cc = c ^ ((r >> 1) & 3);
                cpasync16(sb + (OFF_Q + slot * 2048 + r * 16 + cc * 4) * 4,
                          g_qT + ((ntbase + itq) * 128 + r) * 16 + c * 4);
            }
        }
        asm volatile("cp.async.commit_group;" ::);
    };
    auto issueV = [&](int itv) {            // stage vp tile ntbase+itv into slot itv%3
        if (itv <= 31) {
            int slot = itv % 3;
            int tid2 = tid - 256;
#pragma unroll
            for (int i2 = 0; i2 < 4; i2++) {
                int idx = i2 * 256 + tid2;
                int r = idx >> 4, c = idx & 15;
                cpasync16(sb + (OFF_VP + slot * 4096 + r * 64 + ((c ^ (r & 7)) << 2)) * 4,
                          g_vp + r * 4096 + (ntbase + itv) * 64 + c * 4);
            }
        }
        asm volatile("cp.async.commit_group;" ::);
    };

    auto phase1 = [&](int qslot, int ebuf) {
        const unsigned qbase = sb + (OFF_Q + qslot * 2048) * 4;
#pragma unroll
        for (int gi = 0; gi < 2; gi++) {
            unsigned bfr[2][2][2];
#pragma unroll
            for (int p = 0; p < 2; p++) {
                int r = wnP * 32 + gi * 16 + (l & 15);
                int ch = (2 * p + (l >> 4)) ^ ((r >> 1) & 3);
                unsigned q0, q1, q2, q3;
                ldsm4(q0, q1, q2, q3, qbase + (r * 16 + ch * 4) * 4);
                bfr[0][p][0] = q0; bfr[0][p][1] = q2;
                bfr[1][p][0] = q1; bfr[1][p][1] = q3;
            }
#pragma unroll
            for (int mi = 0; mi < 4; mi++)
#pragma unroll
                for (int h = 0; h < 2; h++) {
                    float a1[4] = {0.0f, 0.0f, 0.0f, 0.0f};
                    mma16816(a1, ap[mi][0], bfr[h][0]);
                    mma16816(a1, ap[mi][1], bfr[h][1]);
                    float e0 = ex2f(a1[0]);
                    float e1 = ex2f(a1[1]);
                    float e2 = ex2f(a1[2]);
                    float e3 = ex2f(a1[3]);
                    int ni = gi * 2 + h;
                    int cwd = wnP * 16 + ni * 4 + t;
                    int r0 = wmP * 64 + mi * 16 + g;
                    int r1 = r0 + 8;
                    smem[OFF_E + ebuf * 8192 + r0 * 64 + swz(r0, cwd)] = packbf(e0, e1);
                    smem[OFF_E + ebuf * 8192 + r1 * 64 + swz(r1, cwd)] = packbf(e2, e3);
                }
        }
    };

    auto phase2 = [&](int vslot, int ebuf) {
        const unsigned vbase = sb + (OFF_VP + vslot * 4096) * 4;
        const unsigned ebase = sb + (OFF_E + ebuf * 8192) * 4;
#pragma unroll
        for (int kk = 0; kk < 4; kk++) {
            int ch = nh * 8 + kk * 2 + (l >> 4);
            unsigned a2[2][4], v2[4][4];
#pragma unroll
            for (int i = 0; i < 2; i++) {
                int r = wm2 * 32 + i * 16 + (l & 15);
                ldsm4(a2[i][0], a2[i][1], a2[i][2], a2[i][3],
                      ebase + (r * 64 + ((ch ^ (r & 7)) << 2)) * 4);
            }
#pragma unroll
            for (int cb = 0; cb < 4; cb++) {
                int r = cb * 16 + (l & 15);
                ldsm4(v2[cb][0], v2[cb][1], v2[cb][2], v2[cb][3],
                      vbase + (r * 64 + ((ch ^ (r & 7)) << 2)) * 4);
            }
#pragma unroll
            for (int i = 0; i < 2; i++)
#pragma unroll
                for (int cb = 0; cb < 4; cb++) {
                    unsigned bl[2] = {v2[cb][0], v2[cb][2]};
                    unsigned bh[2] = {v2[cb][1], v2[cb][3]};
                    mma16816(acc[i][cb * 2],     a2[i], bl);
                    mma16816(acc[i][cb * 2 + 1], a2[i], bh);
                }
        }
    };

    // ---- prologue ----
    if (isP) {
#pragma unroll
        for (int mi = 0; mi < 4; mi++)
#pragma unroll
            for (int kk = 0; kk < 2; kk++) {
                const unsigned* p = g_qT + (m0 + wmP * 64 + mi * 16 + g) * 16 + kk * 8 + t;
                ap[mi][kk][0] = p[0];
                ap[mi][kk][1] = p[128];
                ap[mi][kk][2] = p[4];
                ap[mi][kk][3] = p[132];
            }
        issueQ(0);
        issueQ(1);
        issueQ(2);
        asm volatile("cp.async.wait_group 2;" ::);   // sQ(0) ready
        phase1(0, 0);
    } else {
#pragma unroll
        for (int i = 0; i < 2; i++)
#pragma unroll
            for (int j = 0; j < 8; j++)
                acc[i][j][0] = acc[i][j][1] = acc[i][j][2] = acc[i][j][3] = 0.0f;
        issueV(0);
        issueV(1);
    }
    __syncthreads();

    // ---- main loop: one barrier per iteration ----
    for (int it = 0; it < 32; it++) {
        if (isP) {
            issueQ(it + 3);
            asm volatile("cp.async.wait_group 2;" ::);   // sQ(it+1) ready
            if (it < 31) phase1((it + 1) % 3, (it + 1) & 1);
        } else {
            issueV(it + 2);
            asm volatile("cp.async.wait_group 2;" ::);   // vp(it) ready
            phase2(it % 3, it & 1);
        }
        __syncthreads();
    }

    // ---- epilogue: reduce 2 n-split partials via padded smem ----
    float* sOut = (float*)smem;
    if (!isP) {
        const int rbase = nh * 8448;   // 128*66 words per group
#pragma unroll
        for (int i = 0; i < 2; i++)
#pragma unroll
            for (int j = 0; j < 8; j++) {
                int m = wm2 * 32 + i * 16 + g;
                int c = j * 8 + 2 * t;
                sOut[rbase + m * 66 + c]           = acc[i][j][0];
                sOut[rbase + m * 66 + c + 1]       = acc[i][j][1];
                sOut[rbase + (m + 8) * 66 + c]     = acc[i][j][2];
                sOut[rbase + (m + 8) * 66 + c + 1] = acc[i][j][3];
            }
    }
    __syncthreads();

    float* P = g_P + blockIdx.y * (C_CH * N_TOK);
    const int m = tid & 127;
    const int cb = tid >> 7;   // 0..3
#pragma unroll
    for (int cc = 0; cc < 16; cc++) {
        int c = cb * 16 + cc;
        float s = sOut[m * 66 + c] + sOut[8448 + m * 66 + c];
        P[c * N_TOK + m0 + m] = s;
    }
}

// ---------------- K4: out = x + sum_s P[s] ----------------
__global__ void k4_final(const float* __restrict__ x, float* __restrict__ out) {
    int idx = blockIdx.x * 256 + threadIdx.x;
    float s = x[idx];
#pragma unroll
    for (int sp = 0; sp < NSPLIT; sp++) s += g_P[sp * (C_CH * N_TOK) + idx];
    out[idx] = s;
}

extern "C" void kernel_launch(void* const* d_in, const int* in_sizes, int n_in,
                              void* d_out, int out_size) {
    const float* x    = (const float*)d_in[0];   // [64][8192]
    const float* W    = (const float*)d_in[1];   // [32][64]
    const float* bias = (const float*)d_in[2];   // [32]
    float* out = (float*)d_out;                  // [64][8192]

    cudaFuncSetAttribute(kA_zsum, cudaFuncAttributeMaxDynamicSharedMemorySize, SMEM_KA_BYTES);
    cudaFuncSetAttribute(kB_fused, cudaFuncAttributeMaxDynamicSharedMemorySize, SMEM_KB_BYTES);

    k1_qproj<<<32, 256>>>(x, W, bias);
    kA_zsum<<<136, 512, SMEM_KA_BYTES>>>();
    k2b_vprep<<<1024, 256>>>(x);
    kB_fused<<<dim3(64, NSPLIT), 512, SMEM_KB_BYTES>>>();
    k4_final<<<2048, 256>>>(x, out);
}

// round 13
// speedup vs baseline: 1.1890x; 1.1890x over previous
#include <cuda_runtime.h>
#include <cuda_bf16.h>
#include <cstdint>

#define N_TOK 8192
#define C_CH  64
#define CR_   32
#define NSPLIT 2

// Scratch
__device__ unsigned g_qT[N_TOK * 16];               // [8192][32] bf16, scaled by sqrt(log2e)*32^-0.25
__device__ float    g_Z[N_TOK];                     // row sums of exp(S)
__device__ unsigned g_vp[C_CH * 4096];              // [64][8192] bf16 = x / Z[n]
__device__ __align__(16) float g_P[NSPLIT * C_CH * N_TOK];  // split partials (4MB)

// ---------------- helpers ----------------
static __device__ __forceinline__ float ex2f(float x) {
    float r;
    asm("ex2.approx.f32 %0, %1;" : "=f"(r) : "f"(x));
    return r;
}

static __device__ __forceinline__ unsigned packbf(float lo, float hi) {
    unsigned u;
    asm("cvt.rn.bf16x2.f32 %0, %1, %2;" : "=r"(u) : "f"(hi), "f"(lo));
    return u;
}

static __device__ __forceinline__ unsigned long long packf2(float lo, float hi) {
    unsigned long long r;
    asm("mov.b64 %0, {%1, %2};" : "=l"(r) : "f"(lo), "f"(hi));
    return r;
}
static __device__ __forceinline__ unsigned long long addf2(unsigned long long a, unsigned long long b) {
    unsigned long long r;
    asm("add.rn.f32x2 %0, %1, %2;" : "=l"(r) : "l"(a), "l"(b));
    return r;
}
static __device__ __forceinline__ void unpackf2(unsigned long long v, float& lo, float& hi) {
    asm("mov.b64 {%0, %1}, %2;" : "=f"(lo), "=f"(hi) : "l"(v));
}

static __device__ __forceinline__ void mma16816(float d[4], const unsigned a[4], const unsigned b[2]) {
    asm("mma.sync.aligned.m16n8k16.row.col.f32.bf16.bf16.f32 "
        "{%0,%1,%2,%3}, {%4,%5,%6,%7}, {%8,%9}, {%0,%1,%2,%3};"
        : "+f"(d[0]), "+f"(d[1]), "+f"(d[2]), "+f"(d[3])
        : "r"(a[0]), "r"(a[1]), "r"(a[2]), "r"(a[3]), "r"(b[0]), "r"(b[1]));
}

static __device__ __forceinline__ void ldsm4(unsigned& r0, unsigned& r1, unsigned& r2, unsigned& r3,
                                             unsigned saddr) {
    asm volatile("ldmatrix.sync.aligned.m8n8.x4.shared.b16 {%0,%1,%2,%3}, [%4];"
                 : "=r"(r0), "=r"(r1), "=r"(r2), "=r"(r3) : "r"(saddr));
}

static __device__ __forceinline__ void cpasync16(unsigned saddr, const void* gsrc) {
    asm volatile("cp.async.cg.shared.global [%0], [%1], 16;" :: "r"(saddr), "l"(gsrc));
}

static __device__ __forceinline__ int swz(int r, int w) {
    return (((w >> 2) ^ (r & 7)) << 2) | (w & 3);
}

// ---------------- K1: qT = (W@x + bias) * sqrt(log2e)*32^-0.25, zero Z ----------------
__global__ void k1_qproj(const float* __restrict__ x, const float* __restrict__ W,
                         const float* __restrict__ bias) {
    __shared__ float sW[CR_ * 64];
    __shared__ float sb[CR_];
    int tid = threadIdx.x;
    for (int i = tid; i < CR_ * 64; i += 256) sW[i] = W[i];
    if (tid < CR_) sb[tid] = bias[tid];
    __syncthreads();

    int n = blockIdx.x * 256 + tid;
    float q[CR_];
#pragma unroll
    for (int k = 0; k < CR_; k++) q[k] = sb[k];
#pragma unroll 4
    for (int c = 0; c < 64; c++) {
        float xv = x[c * N_TOK + n];
#pragma unroll
        for (int k = 0; k < CR_; k++) q[k] = fmaf(sW[k * 64 + c], xv, q[k]);
    }
    const float sc = 0.5050097687177836f;  // 32^-0.25 * sqrt(log2 e)
    unsigned* dst = g_qT + n * 16;
#pragma unroll
    for (int k = 0; k < 16; k++) dst[k] = packbf(q[2 * k] * sc, q[2 * k + 1] * sc);
    g_Z[n] = 0.0f;
}

// ---------------- KA: Z = rowsum(exp(S)), triangular, smem-staged, streaming ----------------
__global__ void __launch_bounds__(256, 3) kA_zsum() {
    __shared__ __align__(16) unsigned sQ[2 * 128 * 16];   // 16 KB: [tile i | tile j]
    const int bid = blockIdx.x;
    int ti = (int)((129.0f - sqrtf(16641.0f - 8.0f * (float)bid)) * 0.5f);
    while (ti > 0 && bid < (129 * ti - ti * ti) / 2) ti--;
    while (bid >= (129 * (ti + 1) - (ti + 1) * (ti + 1)) / 2) ti++;
    const int tj = ti + (bid - (129 * ti - ti * ti) / 2);

    const int tid = threadIdx.x;
    const int l = tid & 31, w = tid >> 5;
    const int g = l >> 2, t = l & 3;
    const int wm = w >> 2, wn = w & 3;        // 2 x 4 warps; warp tile 64(i) x 32(j)
    const unsigned sqb = (unsigned)__cvta_generic_to_shared(sQ);

    // stage both q tiles: 1024 x 16B chunks
#pragma unroll
    for (int i2 = 0; i2 < 4; i2++) {
        int idx = i2 * 256 + tid;
        int tile = idx >> 9;
        int rr = (idx >> 2) & 127;
        int ch = idx & 3;
        int cc = ch ^ ((rr >> 1) & 3);
        int srow = (tile ? tj : ti) * 128 + rr;
        cpasync16(sqb + (tile * 2048 + rr * 16 + cc * 4) * 4, g_qT + srow * 16 + ch * 4);
    }
    asm volatile("cp.async.commit_group;" ::);
    asm volatile("cp.async.wait_group 0;" ::);
    __syncthreads();

    const unsigned qib = sqb;
    const unsigned qjb = sqb + 2048 * 4;

    unsigned long long rsp[4][2], csp[4];
#pragma unroll
    for (int i = 0; i < 4; i++) { rsp[i][0] = 0ull; rsp[i][1] = 0ull; csp[i] = 0ull; }

#pragma unroll
    for (int mi = 0; mi < 4; mi++) {
        unsigned a0[4], a1[4];
        {
            int r = wm * 64 + mi * 16 + (l & 15);
            int c0 = ((l >> 4))     ^ ((r >> 1) & 3);
            int c1 = (2 + (l >> 4)) ^ ((r >> 1) & 3);
            ldsm4(a0[0], a0[1], a0[2], a0[3], qib + (r * 16 + c0 * 4) * 4);
            ldsm4(a1[0], a1[1], a1[2], a1[3], qib + (r * 16 + c1 * 4) * 4);
        }
#pragma unroll
        for (int nj = 0; nj < 2; nj++) {
            unsigned v0[4], v1[4];
            {
                int r = wn * 32 + nj * 16 + (l & 15);
                int c0 = ((l >> 4))     ^ ((r >> 1) & 3);
                int c1 = (2 + (l >> 4)) ^ ((r >> 1) & 3);
                ldsm4(v0[0], v0[1], v0[2], v0[3], qjb + (r * 16 + c0 * 4) * 4);
                ldsm4(v1[0], v1[1], v1[2], v1[3], qjb + (r * 16 + c1 * 4) * 4);
            }
#pragma unroll
            for (int h = 0; h < 2; h++) {
                float acc[4] = {0.0f, 0.0f, 0.0f, 0.0f};
                unsigned b0[2] = {v0[h], v0[h + 2]};
                unsigned b1[2] = {v1[h], v1[h + 2]};
                mma16816(acc, a0, b0);
                mma16816(acc, a1, b1);
                float e0 = ex2f(acc[0]);
                float e1 = ex2f(acc[1]);
                float e2 = ex2f(acc[2]);
                float e3 = ex2f(acc[3]);
                unsigned long long p01 = packf2(e0, e1);
                unsigned long long p23 = packf2(e2, e3);
                rsp[mi][0] = addf2(rsp[mi][0], p01);
                rsp[mi][1] = addf2(rsp[mi][1], p23);
                int ni = nj * 2 + h;
                csp[ni] = addf2(csp[ni], addf2(p01, p23));
            }
        }
    }

    const int i0 = ti * 128 + wm * 64;
    const int j0 = tj * 128 + wn * 32;
#pragma unroll
    for (int mi = 0; mi < 4; mi++)
#pragma unroll
        for (int r = 0; r < 2; r++) {
            float lo, hi;
            unpackf2(rsp[mi][r], lo, hi);
            float v = lo + hi;
            v += __shfl_xor_sync(0xffffffffu, v, 1);
            v += __shfl_xor_sync(0xffffffffu, v, 2);
            if (t == 0) atomicAdd(&g_Z[i0 + mi * 16 + r * 8 + g], v);
        }
    if (ti != tj) {
#pragma unroll
        for (int ni = 0; ni < 4; ni++) {
            float cl, ch2;
            unpackf2(csp[ni], cl, ch2);
            float cv[2] = {cl, ch2};
#pragma unroll
            for (int p = 0; p < 2; p++) {
                float v = cv[p];
                v += __shfl_xor_sync(0xffffffffu, v, 4);
                v += __shfl_xor_sync(0xffffffffu, v, 8);
                v += __shfl_xor_sync(0xffffffffu, v, 16);
                if (l < 4) atomicAdd(&g_Z[j0 + ni * 8 + 2 * t + p], v);
            }
        }
    }
}

// ---------------- K2b: vp[c][n] = bf16(x[c][n] / Z[n]) ----------------
__global__ void k2b_vprep(const float* __restrict__ x) {
    int wdx = blockIdx.x * 256 + threadIdx.x;
    int c  = wdx >> 12;
    int nw = wdx & 4095;
    int n  = nw * 2;
    float v0 = x[c * N_TOK + n]     / g_Z[n];
    float v1 = x[c * N_TOK + n + 1] / g_Z[n + 1];
    g_vp[wdx] = packbf(v0, v1);
}

// ---------------- KB: fused E-recompute + out GEMM ----------------
// phase2 operand swap: A = sE rows (m x k=n), B = vp rows (c x k=n) -> D[m][c].
// 16 warps: phase1 4(m)x4(n); phase2 4(m-groups) x 4(n-split).
// fp32 ex2 (accuracy: quantize AFTER exp, never before). 4-slot rotation (&3).
#define SMEM_KB_BYTES 163840
__global__ void __launch_bounds__(512, 1) kB_fused() {
    extern __shared__ __align__(16) unsigned smem[];
    const unsigned OFF_E  = 0;              // 2 * 128*64 = 16384 words
    const unsigned OFF_VP = 16384;          // 4 * 64*64  = 16384 words
    const unsigned OFF_Q  = 32768;          // 4 * 128*16 =  8192 words

    const int tid = threadIdx.x;
    const int l = tid & 31, w = tid >> 5;   // w 0..15
    const int g = l >> 2, t = l & 3;
    const int wm = w >> 2, wn = w & 3;      // phase1: 4(m) x 4(n)
    const int wm2 = w & 3, nq = w >> 2;     // phase2: 4(m-groups) x 4(n-split)
    const int m0 = blockIdx.x * 128;

    const unsigned sb = (unsigned)__cvta_generic_to_shared(smem);

    // preload qT A-fragments for phase1 (constant per CTA)
    unsigned ap[2][2][4];
#pragma unroll
    for (int mi = 0; mi < 2; mi++)
#pragma unroll
        for (int kk = 0; kk < 2; kk++) {
            const unsigned* p = g_qT + (m0 + wm * 32 + mi * 16 + g) * 16 + kk * 8 + t;
            ap[mi][kk][0] = p[0];
            ap[mi][kk][1] = p[128];
            ap[mi][kk][2] = p[4];
            ap[mi][kk][3] = p[132];
        }

    float acc[2][8][4];   // [i: m16][j: c8][frag]
#pragma unroll
    for (int i = 0; i < 2; i++)
#pragma unroll
        for (int j = 0; j < 8; j++)
            acc[i][j][0] = acc[i][j][1] = acc[i][j][2] = acc[i][j][3] = 0.0f;

    const int ntbase = blockIdx.y * 32;

    auto issue = [&](int slot, int nt) {
#pragma unroll
        for (int i2 = 0; i2 < 2; i2++) {
            int idx = i2 * 512 + tid;
            int r = idx >> 4, c = idx & 15;
            cpasync16(sb + (OFF_VP + slot * 4096 + r * 64 + ((c ^ (r & 7)) << 2)) * 4,
                      g_vp + r * 4096 + nt * 64 + c * 4);
        }
        {
            int r = tid >> 2, c = tid & 3;
            int cc = c ^ ((r >> 1) & 3);
            cpasync16(sb + (OFF_Q + slot * 2048 + r * 16 + cc * 4) * 4,
                      g_qT + (nt * 128 + r) * 16 + c * 4);
        }
        asm volatile("cp.async.commit_group;" ::);
    };

    auto phase1 = [&](int qslot, int ebuf) {
        const unsigned qbase = sb + (OFF_Q + qslot * 2048) * 4;
#pragma unroll
        for (int gi = 0; gi < 2; gi++) {
            unsigned bfr[2][2][2];
#pragma unroll
            for (int p = 0; p < 2; p++) {
                int r = wn * 32 + gi * 16 + (l & 15);
                int ch = (2 * p + (l >> 4)) ^ ((r >> 1) & 3);
                unsigned q0, q1, q2, q3;
                ldsm4(q0, q1, q2, q3, qbase + (r * 16 + ch * 4) * 4);
                bfr[0][p][0] = q0; bfr[0][p][1] = q2;
                bfr[1][p][0] = q1; bfr[1][p][1] = q3;
            }
#pragma unroll
            for (int mi = 0; mi < 2; mi++)
#pragma unroll
                for (int h = 0; h < 2; h++) {
                    float a1[4] = {0.0f, 0.0f, 0.0f, 0.0f};
                    mma16816(a1, ap[mi][0], bfr[h][0]);
                    mma16816(a1, ap[mi][1], bfr[h][1]);
                    float e0 = ex2f(a1[0]);
                    float e1 = ex2f(a1[1]);
                    float e2 = ex2f(a1[2]);
                    float e3 = ex2f(a1[3]);
                    int ni = gi * 2 + h;
                    int cwd = wn * 16 + ni * 4 + t;
                    int r0 = wm * 32 + mi * 16 + g;
                    int r1 = r0 + 8;
                    smem[OFF_E + ebuf * 8192 + r0 * 64 + swz(r0, cwd)] = packbf(e0, e1);
                    smem[OFF_E + ebuf * 8192 + r1 * 64 + swz(r1, cwd)] = packbf(e2, e3);
                }
        }
    };

    // phase2: acc[m][c] += sE(m, n-quarter) * vp(c, n-quarter)
    auto phase2 = [&](int vslot, int ebuf) {
        const unsigned vbase = sb + (OFF_VP + vslot * 4096) * 4;
        const unsigned ebase = sb + (OFF_E + ebuf * 8192) * 4;
#pragma unroll
        for (int kk = 0; kk < 2; kk++) {
            int ch = nq * 4 + kk * 2 + (l >> 4);
            unsigned a2[2][4], v2[4][4];
#pragma unroll
            for (int i = 0; i < 2; i++) {
                int r = wm2 * 32 + i * 16 + (l & 15);
                ldsm4(a2[i][0], a2[i][1], a2[i][2], a2[i][3],
                      ebase + (r * 64 + ((ch ^ (r & 7)) << 2)) * 4);
            }
#pragma unroll
            for (int cb = 0; cb < 4; cb++) {
                int r = cb * 16 + (l & 15);
                ldsm4(v2[cb][0], v2[cb][1], v2[cb][2], v2[cb][3],
                      vbase + (r * 64 + ((ch ^ (r & 7)) << 2)) * 4);
            }
#pragma unroll
            for (int i = 0; i < 2; i++)
#pragma unroll
                for (int cb = 0; cb < 4; cb++) {
                    unsigned bl[2] = {v2[cb][0], v2[cb][2]};
                    unsigned bh[2] = {v2[cb][1], v2[cb][3]};
                    mma16816(acc[i][cb * 2],     a2[i], bl);
                    mma16816(acc[i][cb * 2 + 1], a2[i], bh);
                }
        }
    };

    // prologue
    issue(0, ntbase);
    issue(1, ntbase + 1);
    asm volatile("cp.async.wait_group 1;" ::);
    __syncthreads();
    phase1(0, 0);

#pragma unroll 4
    for (int it = 0; it < 32; it++) {
        asm volatile("cp.async.wait_group 0;" ::);
        __syncthreads();
        if (it <= 29) issue((it + 2) & 3, ntbase + it + 2);
        phase2(it & 3, it & 1);
        if (it < 31) phase1((it + 1) & 3, (it + 1) & 1);
    }

    // epilogue: reduce 4 n-split partials via padded smem (stride 66), write g_P
    __syncthreads();
    float* sOut = (float*)smem;
    const int rbase = nq * 8448;   // 128*66 words per group
#pragma unroll
    for (int i = 0; i < 2; i++)
#pragma unroll
        for (int j = 0; j < 8; j++) {
            int m = wm2 * 32 + i * 16 + g;
            int c = j * 8 + 2 * t;
            sOut[rbase + m * 66 + c]           = acc[i][j][0];
            sOut[rbase + m * 66 + c + 1]       = acc[i][j][1];
            sOut[rbase + (m + 8) * 66 + c]     = acc[i][j][2];
            sOut[rbase + (m + 8) * 66 + c + 1] = acc[i][j][3];
        }
    __syncthreads();

    float* P = g_P + blockIdx.y * (C_CH * N_TOK);
    const int m = tid & 127;
    const int cb = tid >> 7;   // 0..3
#pragma unroll
    for (int cc = 0; cc < 16; cc++) {
        int c = cb * 16 + cc;
        float s = sOut[m * 66 + c] + sOut[8448 + m * 66 + c] +
                  sOut[16896 + m * 66 + c] + sOut[25344 + m * 66 + c];
        P[c * N_TOK + m0 + m] = s;
    }
}

// ---------------- K4: out = x + sum_s P[s] ----------------
__global__ void k4_final(const float* __restrict__ x, float* __restrict__ out) {
    int idx = blockIdx.x * 256 + threadIdx.x;
    float s = x[idx];
#pragma unroll
    for (int sp = 0; sp < NSPLIT; sp++) s += g_P[sp * (C_CH * N_TOK) + idx];
    out[idx] = s;
}

extern "C" void kernel_launch(void* const* d_in, const int* in_sizes, int n_in,
                              void* d_out, int out_size) {
    const float* x    = (const float*)d_in[0];   // [64][8192]
    const float* W    = (const float*)d_in[1];   // [32][64]
    const float* bias = (const float*)d_in[2];   // [32]
    float* out = (float*)d_out;                  // [64][8192]

    cudaFuncSetAttribute(kB_fused, cudaFuncAttributeMaxDynamicSharedMemorySize, SMEM_KB_BYTES);

    k1_qproj<<<32, 256>>>(x, W, bias);
    kA_zsum<<<2080, 256>>>();
    k2b_vprep<<<1024, 256>>>(x);
    kB_fused<<<dim3(64, NSPLIT), 512, SMEM_KB_BYTES>>>();
    k4_final<<<2048, 256>>>(x, out);
}

// round 14
// speedup vs baseline: 1.1916x; 1.0022x over previous
#include <cuda_runtime.h>
#include <cuda_bf16.h>
#include <cstdint>

#define N_TOK 8192
#define C_CH  64
#define CR_   32
#define NSPLIT 2

// Scratch
__device__ unsigned g_qT[N_TOK * 16];               // [8192][32] bf16, scaled by sqrt(log2e)*32^-0.25
__device__ float    g_Z[N_TOK];                     // row sums of exp(S)
__device__ unsigned g_vp[C_CH * 4096];              // [64][8192] bf16 = x / Z[n]
__device__ __align__(16) float g_P[NSPLIT * C_CH * N_TOK];  // split partials (4MB)

// ---------------- helpers ----------------
static __device__ __forceinline__ float ex2f(float x) {
    float r;
    asm("ex2.approx.f32 %0, %1;" : "=f"(r) : "f"(x));
    return r;
}

static __device__ __forceinline__ unsigned packbf(float lo, float hi) {
    unsigned u;
    asm("cvt.rn.bf16x2.f32 %0, %1, %2;" : "=r"(u) : "f"(hi), "f"(lo));
    return u;
}

static __device__ __forceinline__ unsigned long long packf2(float lo, float hi) {
    unsigned long long r;
    asm("mov.b64 %0, {%1, %2};" : "=l"(r) : "f"(lo), "f"(hi));
    return r;
}
static __device__ __forceinline__ unsigned long long addf2(unsigned long long a, unsigned long long b) {
    unsigned long long r;
    asm("add.rn.f32x2 %0, %1, %2;" : "=l"(r) : "l"(a), "l"(b));
    return r;
}
static __device__ __forceinline__ void unpackf2(unsigned long long v, float& lo, float& hi) {
    asm("mov.b64 {%0, %1}, %2;" : "=f"(lo), "=f"(hi) : "l"(v));
}

static __device__ __forceinline__ void mma16816(float d[4], const unsigned a[4], const unsigned b[2]) {
    asm("mma.sync.aligned.m16n8k16.row.col.f32.bf16.bf16.f32 "
        "{%0,%1,%2,%3}, {%4,%5,%6,%7}, {%8,%9}, {%0,%1,%2,%3};"
        : "+f"(d[0]), "+f"(d[1]), "+f"(d[2]), "+f"(d[3])
        : "r"(a[0]), "r"(a[1]), "r"(a[2]), "r"(a[3]), "r"(b[0]), "r"(b[1]));
}

static __device__ __forceinline__ void ldsm4(unsigned& r0, unsigned& r1, unsigned& r2, unsigned& r3,
                                             unsigned saddr) {
    asm volatile("ldmatrix.sync.aligned.m8n8.x4.shared.b16 {%0,%1,%2,%3}, [%4];"
                 : "=r"(r0), "=r"(r1), "=r"(r2), "=r"(r3) : "r"(saddr));
}

static __device__ __forceinline__ void cpasync16(unsigned saddr, const void* gsrc) {
    asm volatile("cp.async.cg.shared.global [%0], [%1], 16;" :: "r"(saddr), "l"(gsrc));
}

static __device__ __forceinline__ int swz(int r, int w) {
    return (((w >> 2) ^ (r & 7)) << 2) | (w & 3);
}

// ---------------- K1: qT = (W@x + bias) * sqrt(log2e)*32^-0.25, zero Z ----------------
__global__ void k1_qproj(const float* __restrict__ x, const float* __restrict__ W,
                         const float* __restrict__ bias) {
    __shared__ float sW[CR_ * 64];
    __shared__ float sb[CR_];
    int tid = threadIdx.x;
    for (int i = tid; i < CR_ * 64; i += 256) sW[i] = W[i];
    if (tid < CR_) sb[tid] = bias[tid];
    __syncthreads();

    int n = blockIdx.x * 256 + tid;
    float q[CR_];
#pragma unroll
    for (int k = 0; k < CR_; k++) q[k] = sb[k];
#pragma unroll 4
    for (int c = 0; c < 64; c++) {
        float xv = x[c * N_TOK + n];
#pragma unroll
        for (int k = 0; k < CR_; k++) q[k] = fmaf(sW[k * 64 + c], xv, q[k]);
    }
    const float sc = 0.5050097687177836f;  // 32^-0.25 * sqrt(log2 e)
    unsigned* dst = g_qT + n * 16;
#pragma unroll
    for (int k = 0; k < 16; k++) dst[k] = packbf(q[2 * k] * sc, q[2 * k + 1] * sc);
    g_Z[n] = 0.0f;
}

// ---------------- KA: Z = rowsum(exp(S)), triangular, smem-staged, streaming ----------------
__global__ void __launch_bounds__(256, 3) kA_zsum() {
    __shared__ __align__(16) unsigned sQ[2 * 128 * 16];   // 16 KB: [tile i | tile j]
    const int bid = blockIdx.x;
    int ti = (int)((129.0f - sqrtf(16641.0f - 8.0f * (float)bid)) * 0.5f);
    while (ti > 0 && bid < (129 * ti - ti * ti) / 2) ti--;
    while (bid >= (129 * (ti + 1) - (ti + 1) * (ti + 1)) / 2) ti++;
    const int tj = ti + (bid - (129 * ti - ti * ti) / 2);

    const int tid = threadIdx.x;
    const int l = tid & 31, w = tid >> 5;
    const int g = l >> 2, t = l & 3;
    const int wm = w >> 2, wn = w & 3;        // 2 x 4 warps; warp tile 64(i) x 32(j)
    const unsigned sqb = (unsigned)__cvta_generic_to_shared(sQ);

    // stage both q tiles: 1024 x 16B chunks
#pragma unroll
    for (int i2 = 0; i2 < 4; i2++) {
        int idx = i2 * 256 + tid;
        int tile = idx >> 9;
        int rr = (idx >> 2) & 127;
        int ch = idx & 3;
        int cc = ch ^ ((rr >> 1) & 3);
        int srow = (tile ? tj : ti) * 128 + rr;
        cpasync16(sqb + (tile * 2048 + rr * 16 + cc * 4) * 4, g_qT + srow * 16 + ch * 4);
    }
    asm volatile("cp.async.commit_group;" ::);
    asm volatile("cp.async.wait_group 0;" ::);
    __syncthreads();

    const unsigned qib = sqb;
    const unsigned qjb = sqb + 2048 * 4;

    unsigned long long rsp[4][2], csp[4];
#pragma unroll
    for (int i = 0; i < 4; i++) { rsp[i][0] = 0ull; rsp[i][1] = 0ull; csp[i] = 0ull; }

#pragma unroll
    for (int mi = 0; mi < 4; mi++) {
        unsigned a0[4], a1[4];
        {
            int r = wm * 64 + mi * 16 + (l & 15);
            int c0 = ((l >> 4))     ^ ((r >> 1) & 3);
            int c1 = (2 + (l >> 4)) ^ ((r >> 1) & 3);
            ldsm4(a0[0], a0[1], a0[2], a0[3], qib + (r * 16 + c0 * 4) * 4);
            ldsm4(a1[0], a1[1], a1[2], a1[3], qib + (r * 16 + c1 * 4) * 4);
        }
#pragma unroll
        for (int nj = 0; nj < 2; nj++) {
            unsigned v0[4], v1[4];
            {
                int r = wn * 32 + nj * 16 + (l & 15);
                int c0 = ((l >> 4))     ^ ((r >> 1) & 3);
                int c1 = (2 + (l >> 4)) ^ ((r >> 1) & 3);
                ldsm4(v0[0], v0[1], v0[2], v0[3], qjb + (r * 16 + c0 * 4) * 4);
                ldsm4(v1[0], v1[1], v1[2], v1[3], qjb + (r * 16 + c1 * 4) * 4);
            }
#pragma unroll
            for (int h = 0; h < 2; h++) {
                float acc[4] = {0.0f, 0.0f, 0.0f, 0.0f};
                unsigned b0[2] = {v0[h], v0[h + 2]};
                unsigned b1[2] = {v1[h], v1[h + 2]};
                mma16816(acc, a0, b0);
                mma16816(acc, a1, b1);
                float e0 = ex2f(acc[0]);
                float e1 = ex2f(acc[1]);
                float e2 = ex2f(acc[2]);
                float e3 = ex2f(acc[3]);
                unsigned long long p01 = packf2(e0, e1);
                unsigned long long p23 = packf2(e2, e3);
                rsp[mi][0] = addf2(rsp[mi][0], p01);
                rsp[mi][1] = addf2(rsp[mi][1], p23);
                int ni = nj * 2 + h;
                csp[ni] = addf2(csp[ni], addf2(p01, p23));
            }
        }
    }

    const int i0 = ti * 128 + wm * 64;
    const int j0 = tj * 128 + wn * 32;
#pragma unroll
    for (int mi = 0; mi < 4; mi++)
#pragma unroll
        for (int r = 0; r < 2; r++) {
            float lo, hi;
            unpackf2(rsp[mi][r], lo, hi);
            float v = lo + hi;
            v += __shfl_xor_sync(0xffffffffu, v, 1);
            v += __shfl_xor_sync(0xffffffffu, v, 2);
            if (t == 0) atomicAdd(&g_Z[i0 + mi * 16 + r * 8 + g], v);
        }
    if (ti != tj) {
#pragma unroll
        for (int ni = 0; ni < 4; ni++) {
            float cl, ch2;
            unpackf2(csp[ni], cl, ch2);
            float cv[2] = {cl, ch2};
#pragma unroll
            for (int p = 0; p < 2; p++) {
                float v = cv[p];
                v += __shfl_xor_sync(0xffffffffu, v, 4);
                v += __shfl_xor_sync(0xffffffffu, v, 8);
                v += __shfl_xor_sync(0xffffffffu, v, 16);
                if (l < 4) atomicAdd(&g_Z[j0 + ni * 8 + 2 * t + p], v);
            }
        }
    }
}

// ---------------- K2b: vp[c][n] = bf16(x[c][n] / Z[n]) ----------------
__global__ void k2b_vprep(const float* __restrict__ x) {
    int wdx = blockIdx.x * 256 + threadIdx.x;
    int c  = wdx >> 12;
    int nw = wdx & 4095;
    int n  = nw * 2;
    float v0 = x[c * N_TOK + n]     / g_Z[n];
    float v1 = x[c * N_TOK + n + 1] / g_Z[n + 1];
    g_vp[wdx] = packbf(v0, v1);
}

// ---------------- KB: fused E-recompute + out GEMM ----------------
// phase2 operand swap: A = sE rows (m x k=n), B = vp rows (c x k=n) -> D[m][c].
// 16 warps: phase1 4(m)x4(n); phase2 4(m-groups) x 4(n-split).
// fp32 ex2 (accuracy: quantize AFTER exp, never before). 4-slot rotation (&3).
#define SMEM_KB_BYTES 163840
__global__ void __launch_bounds__(512, 1) kB_fused() {
    extern __shared__ __align__(16) unsigned smem[];
    const unsigned OFF_E  = 0;              // 2 * 128*64 = 16384 words
    const unsigned OFF_VP = 16384;          // 4 * 64*64  = 16384 words
    const unsigned OFF_Q  = 32768;          // 4 * 128*16 =  8192 words

    const int tid = threadIdx.x;
    const int l = tid & 31, w = tid >> 5;   // w 0..15
    const int g = l >> 2, t = l & 3;
    const int wm = w >> 2, wn = w & 3;      // phase1: 4(m) x 4(n)
    const int wm2 = w & 3, nq = w >> 2;     // phase2: 4(m-groups) x 4(n-split)
    const int m0 = blockIdx.x * 128;

    const unsigned sb = (unsigned)__cvta_generic_to_shared(smem);

    // preload qT A-fragments for phase1 (constant per CTA)
    unsigned ap[2][2][4];
#pragma unroll
    for (int mi = 0; mi < 2; mi++)
#pragma unroll
        for (int kk = 0; kk < 2; kk++) {
            const unsigned* p = g_qT + (m0 + wm * 32 + mi * 16 + g) * 16 + kk * 8 + t;
            ap[mi][kk][0] = p[0];
            ap[mi][kk][1] = p[128];
            ap[mi][kk][2] = p[4];
            ap[mi][kk][3] = p[132];
        }

    float acc[2][8][4];   // [i: m16][j: c8][frag]
#pragma unroll
    for (int i = 0; i < 2; i++)
#pragma unroll
        for (int j = 0; j < 8; j++)
            acc[i][j][0] = acc[i][j][1] = acc[i][j][2] = acc[i][j][3] = 0.0f;

    const int ntbase = blockIdx.y * 32;

    auto issue = [&](int slot, int nt) {
#pragma unroll
        for (int i2 = 0; i2 < 2; i2++) {
            int idx = i2 * 512 + tid;
            int r = idx >> 4, c = idx & 15;
            cpasync16(sb + (OFF_VP + slot * 4096 + r * 64 + ((c ^ (r & 7)) << 2)) * 4,
                      g_vp + r * 4096 + nt * 64 + c * 4);
        }
        {
            int r = tid >> 2, c = tid & 3;
            int cc = c ^ ((r >> 1) & 3);
            cpasync16(sb + (OFF_Q + slot * 2048 + r * 16 + cc * 4) * 4,
                      g_qT + (nt * 128 + r) * 16 + c * 4);
        }
        asm volatile("cp.async.commit_group;" ::);
    };

    auto phase1 = [&](int qslot, int ebuf) {
        const unsigned qbase = sb + (OFF_Q + qslot * 2048) * 4;
#pragma unroll
        for (int gi = 0; gi < 2; gi++) {
            unsigned bfr[2][2][2];
#pragma unroll
            for (int p = 0; p < 2; p++) {
                int r = wn * 32 + gi * 16 + (l & 15);
                int ch = (2 * p + (l >> 4)) ^ ((r >> 1) & 3);
                unsigned q0, q1, q2, q3;
                ldsm4(q0, q1, q2, q3, qbase + (r * 16 + ch * 4) * 4);
                bfr[0][p][0] = q0; bfr[0][p][1] = q2;
                bfr[1][p][0] = q1; bfr[1][p][1] = q3;
            }
#pragma unroll
            for (int mi = 0; mi < 2; mi++)
#pragma unroll
                for (int h = 0; h < 2; h++) {
                    float a1[4] = {0.0f, 0.0f, 0.0f, 0.0f};
                    mma16816(a1, ap[mi][0], bfr[h][0]);
                    mma16816(a1, ap[mi][1], bfr[h][1]);
                    float e0 = ex2f(a1[0]);
                    float e1 = ex2f(a1[1]);
                    float e2 = ex2f(a1[2]);
                    float e3 = ex2f(a1[3]);
                    int ni = gi * 2 + h;
                    int cwd = wn * 16 + ni * 4 + t;
                    int r0 = wm * 32 + mi * 16 + g;
                    int r1 = r0 + 8;
                    smem[OFF_E + ebuf * 8192 + r0 * 64 + swz(r0, cwd)] = packbf(e0, e1);
                    smem[OFF_E + ebuf * 8192 + r1 * 64 + swz(r1, cwd)] = packbf(e2, e3);
                }
        }
    };

    // phase2: acc[m][c] += sE(m, n-quarter) * vp(c, n-quarter)
    auto phase2 = [&](int vslot, int ebuf) {
        const unsigned vbase = sb + (OFF_VP + vslot * 4096) * 4;
        const unsigned ebase = sb + (OFF_E + ebuf * 8192) * 4;
#pragma unroll
        for (int kk = 0; kk < 2; kk++) {
            int ch = nq * 4 + kk * 2 + (l >> 4);
            unsigned a2[2][4], v2[4][4];
#pragma unroll
            for (int i = 0; i < 2; i++) {
                int r = wm2 * 32 + i * 16 + (l & 15);
                ldsm4(a2[i][0], a2[i][1], a2[i][2], a2[i][3],
                      ebase + (r * 64 + ((ch ^ (r & 7)) << 2)) * 4);
            }
#pragma unroll
            for (int cb = 0; cb < 4; cb++) {
                int r = cb * 16 + (l & 15);
                ldsm4(v2[cb][0], v2[cb][1], v2[cb][2], v2[cb][3],
                      vbase + (r * 64 + ((ch ^ (r & 7)) << 2)) * 4);
            }
#pragma unroll
            for (int i = 0; i < 2; i++)
#pragma unroll
                for (int cb = 0; cb < 4; cb++) {
                    unsigned bl[2] = {v2[cb][0], v2[cb][2]};
                    unsigned bh[2] = {v2[cb][1], v2[cb][3]};
                    mma16816(acc[i][cb * 2],     a2[i], bl);
                    mma16816(acc[i][cb * 2 + 1], a2[i], bh);
                }
        }
    };

    // prologue
    issue(0, ntbase);
    issue(1, ntbase + 1);
    asm volatile("cp.async.wait_group 1;" ::);
    __syncthreads();
    phase1(0, 0);

#pragma unroll 4
    for (int it = 0; it < 32; it++) {
        asm volatile("cp.async.wait_group 0;" ::);
        __syncthreads();
        if (it <= 29) issue((it + 2) & 3, ntbase + it + 2);
        phase2(it & 3, it & 1);
        if (it < 31) phase1((it + 1) & 3, (it + 1) & 1);
    }

    // epilogue: reduce 4 n-split partials via padded smem (stride 66), write g_P
    __syncthreads();
    float* sOut = (float*)smem;
    const int rbase = nq * 8448;   // 128*66 words per group
#pragma unroll
    for (int i = 0; i < 2; i++)
#pragma unroll
        for (int j = 0; j < 8; j++) {
            int m = wm2 * 32 + i * 16 + g;
            int c = j * 8 + 2 * t;
            sOut[rbase + m * 66 + c]           = acc[i][j][0];
            sOut[rbase + m * 66 + c + 1]       = acc[i][j][1];
            sOut[rbase + (m + 8) * 66 + c]     = acc[i][j][2];
            sOut[rbase + (m + 8) * 66 + c + 1] = acc[i][j][3];
        }
    __syncthreads();

    float* P = g_P + blockIdx.y * (C_CH * N_TOK);
    const int m = tid & 127;
    const int cb = tid >> 7;   // 0..3
#pragma unroll
    for (int cc = 0; cc < 16; cc++) {
        int c = cb * 16 + cc;
        float s = sOut[m * 66 + c] + sOut[8448 + m * 66 + c] +
                  sOut[16896 + m * 66 + c] + sOut[25344 + m * 66 + c];
        P[c * N_TOK + m0 + m] = s;
    }
}

// ---------------- K4: out = x + sum_s P[s] ----------------
__global__ void k4_final(const float* __restrict__ x, float* __restrict__ out) {
    int idx = blockIdx.x * 256 + threadIdx.x;
    float s = x[idx];
#pragma unroll
    for (int sp = 0; sp < NSPLIT; sp++) s += g_P[sp * (C_CH * N_TOK) + idx];
    out[idx] = s;
}

extern "C" void kernel_launch(void* const* d_in, const int* in_sizes, int n_in,
                              void* d_out, int out_size) {
    const float* x    = (const float*)d_in[0];   // [64][8192]
    const float* W    = (const float*)d_in[1];   // [32][64]
    const float* bias = (const float*)d_in[2];   // [32]
    float* out = (float*)d_out;                  // [64][8192]

    cudaFuncSetAttribute(kB_fused, cudaFuncAttributeMaxDynamicSharedMemorySize, SMEM_KB_BYTES);

    k1_qproj<<<32, 256>>>(x, W, bias);
    kA_zsum<<<2080, 256>>>();
    k2b_vprep<<<1024, 256>>>(x);
    kB_fused<<<dim3(64, NSPLIT), 512, SMEM_KB_BYTES>>>();
    k4_final<<<2048, 256>>>(x, out);
}